// round 1
// baseline (speedup 1.0000x reference)
#include <cuda_runtime.h>
#include <math.h>

#define BB   8
#define HH   256
#define WW   256
#define HW   (HH*WW)

// Scratch (no allocations allowed): squared column distances, per-row partials.
__device__ float g_d2p[BB*HW];
__device__ float g_d2n[BB*HW];
__device__ float g_part_pred[BB*HH];
__device__ float g_part_w[BB*HH];
__device__ float g_part_cnt[BB*HH];

// ---------------------------------------------------------------------------
// Pass 1: along H. For feature in {0,BIG}, min-plus envelope == squared integer
// distance to nearest feature pixel in the column (BIG if none). Forward +
// backward scan per (b,w) column. Exact vs reference.
// ---------------------------------------------------------------------------
__global__ void pass1_kernel(const int* __restrict__ targets) {
    int tid = blockIdx.x * blockDim.x + threadIdx.x;   // 0..2047
    int b = tid >> 8;
    int w = tid & 255;
    const int* tc = targets + b * HW + w;
    float* dp = g_d2p + b * HW + w;
    float* dn = g_d2n + b * HW + w;

    int lastp = -1000000, lastn = -1000000;
    for (int h = 0; h < HH; h++) {
        int t = tc[h * WW];
        if (t == 1) lastp = h; else lastn = h;
        dp[h * WW] = (float)(h - lastp);
        dn[h * WW] = (float)(h - lastn);
    }
    int nextp = 1000000, nextn = 1000000;
    for (int h = HH - 1; h >= 0; h--) {
        int t = tc[h * WW];
        if (t == 1) nextp = h; else nextn = h;

        float d1 = dp[h * WW];
        float d2 = (float)(nextp - h);
        float d  = fminf(d1, d2);
        dp[h * WW] = (d > 255.0f) ? 1e9f : d * d;

        d1 = dn[h * WW];
        d2 = (float)(nextn - h);
        d  = fminf(d1, d2);
        dn[h * WW] = (d > 255.0f) ? 1e9f : d * d;
    }
}

// ---------------------------------------------------------------------------
// Pass 2: along W, brute-force lower envelope (exact fp32 match to reference),
// fused with pred/sigmoid, signed distance weighting, and per-row reduction.
// One block per (b,h) row; 256 threads, one output pixel each.
// ---------------------------------------------------------------------------
__global__ void __launch_bounds__(256) pass2_kernel(
    const float* __restrict__ logits, const int* __restrict__ targets) {
    int row = blockIdx.x;          // b*256 + h
    int b   = row >> 8;
    int h   = row & 255;
    int w   = threadIdx.x;

    __shared__ float4 sp4[64];
    __shared__ float4 sn4[64];
    ((float*)sp4)[w] = g_d2p[row * WW + w];
    ((float*)sn4)[w] = g_d2n[row * WW + w];
    __syncthreads();

    float minp = 3.0e38f, minn = 3.0e38f;
    float t = (float)w;            // t = w - j, decremented each step
#pragma unroll 8
    for (int j4 = 0; j4 < 64; j4++) {
        float4 p = sp4[j4];
        float4 n = sn4[j4];
        minp = fminf(minp, fmaf(t, t, p.x)); minn = fminf(minn, fmaf(t, t, n.x)); t -= 1.0f;
        minp = fminf(minp, fmaf(t, t, p.y)); minn = fminf(minn, fmaf(t, t, n.y)); t -= 1.0f;
        minp = fminf(minp, fmaf(t, t, p.z)); minn = fminf(minn, fmaf(t, t, n.z)); t -= 1.0f;
        minp = fminf(minp, fmaf(t, t, p.w)); minn = fminf(minn, fmaf(t, t, n.w)); t -= 1.0f;
    }

    // pred = softmax(logits,axis=1)[:,1] = sigmoid(l1 - l0)
    float l0 = logits[((b * 2 + 0) * HH + h) * WW + w];
    float l1 = logits[((b * 2 + 1) * HH + h) * WW + w];
    float pred = 1.0f / (1.0f + expf(l0 - l1));

    int gt = (targets[row * WW + w] == 1) ? 1 : 0;

    float sdt = sqrtf(minp) - sqrtf(minn);
    float wv  = pred * sdt;
    float cv  = (float)gt;

    // Deterministic block reduction: warp shuffles then cross-warp via shared.
    unsigned m = 0xFFFFFFFFu;
#pragma unroll
    for (int o = 16; o > 0; o >>= 1) {
        pred += __shfl_down_sync(m, pred, o);
        wv   += __shfl_down_sync(m, wv, o);
        cv   += __shfl_down_sync(m, cv, o);
    }
    __shared__ float r0[8], r1[8], r2[8];
    if ((w & 31) == 0) {
        r0[w >> 5] = pred; r1[w >> 5] = wv; r2[w >> 5] = cv;
    }
    __syncthreads();
    if (w == 0) {
        float s0 = 0.f, s1 = 0.f, s2 = 0.f;
#pragma unroll
        for (int i = 0; i < 8; i++) { s0 += r0[i]; s1 += r1[i]; s2 += r2[i]; }
        g_part_pred[row] = s0;
        g_part_w[row]    = s1;
        g_part_cnt[row]  = s2;
    }
}

// ---------------------------------------------------------------------------
// Final: reduce 256 row-partials per image, apply the s==0 / s==size select,
// average over batch. Single block, deterministic.
// ---------------------------------------------------------------------------
__global__ void final_kernel(float* __restrict__ out) {
    int t = threadIdx.x;           // 256 threads
    __shared__ float red[256];
    float total = 0.0f;

    for (int b = 0; b < BB; b++) {
        float sp = g_part_pred[b * HH + t];
        float sw = g_part_w[b * HH + t];
        float sc = g_part_cnt[b * HH + t];

        // reduce sp
        red[t] = sp; __syncthreads();
        for (int s = 128; s > 0; s >>= 1) { if (t < s) red[t] += red[t + s]; __syncthreads(); }
        float Sp = red[0]; __syncthreads();
        // reduce sw
        red[t] = sw; __syncthreads();
        for (int s = 128; s > 0; s >>= 1) { if (t < s) red[t] += red[t + s]; __syncthreads(); }
        float Sw = red[0]; __syncthreads();
        // reduce sc
        red[t] = sc; __syncthreads();
        for (int s = 128; s > 0; s >>= 1) { if (t < s) red[t] += red[t + s]; __syncthreads(); }
        float Sc = red[0]; __syncthreads();

        if (t == 0) {
            float inv = 1.0f / (float)HW;
            float mean_pred = Sp * inv;
            float mean_w    = Sw * inv;
            float per_b;
            if (Sc == 0.0f)                per_b = mean_pred;
            else if (Sc == (float)HW)      per_b = 1.0f - mean_pred;
            else                           per_b = mean_w;
            total += per_b;
        }
    }
    if (t == 0) out[0] = total / (float)BB;
}

extern "C" void kernel_launch(void* const* d_in, const int* in_sizes, int n_in,
                              void* d_out, int out_size) {
    const float* logits  = (const float*)d_in[0];
    const int*   targets = (const int*)d_in[1];
    float*       out     = (float*)d_out;

    pass1_kernel<<<8, 256>>>(targets);
    pass2_kernel<<<BB * HH, 256>>>(logits, targets);
    final_kernel<<<1, 256>>>(out);
}

// round 2
// speedup vs baseline: 5.0795x; 5.0795x over previous
#include <cuda_runtime.h>
#include <math.h>

#define BB   8
#define HH   256
#define WW   256
#define HW   (HH*WW)

// Scratch (no device allocations allowed): per-row reduction partials.
__device__ float g_part_pred[BB*HH];
__device__ float g_part_w[BB*HH];
__device__ float g_part_cnt[BB*HH];

// ---------------------------------------------------------------------------
// Fused kernel: one block per (b,h) row, one thread per pixel.
//  1. Vertical early-exit search: exact nearest-1 / nearest-0 distance along H
//     (identical to reference's min-plus pass over axis 1 on {0,BIG} input:
//      found  -> exact integer distance squared; none -> exactly 1e9).
//  2. Horizontal early-exit lower envelope over smem (exact: once r^2 >= best,
//     no larger radius can win since column distances are >= 0; all finite
//     candidates are exact integers in fp32, so the min is order-independent).
//  3. Fused sigmoid/pred, signed-distance weighting, deterministic reduction.
// ---------------------------------------------------------------------------
__global__ void __launch_bounds__(256) fused_kernel(
    const float* __restrict__ logits, const int* __restrict__ targets) {
    int row = blockIdx.x;          // b*256 + h
    int b   = row >> 8;
    int h   = row & 255;
    int w   = threadIdx.x;

    const int* tcol = targets + b * HW + w;   // column w of image b, stride WW
    int me = tcol[h * WW];

    // ---- vertical search: nearest 1 (r1) and nearest 0 (r0) along H ----
    int r1 = 256, r0 = 256;                    // 256 = "not found"
    if (me == 1) r1 = 0; else r0 = 0;
#pragma unroll 1
    for (int r = 1; r < HH; r++) {
        if (r1 < 256 && r0 < 256) break;       // both resolved (warp-coherent-ish)
        int up = h - r, dn = h + r;
        if (up >= 0) {
            int t = tcol[up * WW];
            if (t == 1) { if (r1 == 256) r1 = r; }
            else        { if (r0 == 256) r0 = r; }
        }
        if (dn < HH) {
            int t = tcol[dn * WW];
            if (t == 1) { if (r1 == 256) r1 = r; }
            else        { if (r0 == 256) r0 = r; }
        }
    }
    float d2p = (r1 < 256) ? (float)(r1 * r1) : 1e9f;   // dist^2 to nearest fg in column
    float d2n = (r0 < 256) ? (float)(r0 * r0) : 1e9f;   // dist^2 to nearest bg in column

    // ---- horizontal lower envelope with BIG-padded smem (no bounds checks) ----
    __shared__ float sp[3 * WW];
    __shared__ float sn[3 * WW];
    sp[w] = 1e9f; sp[2 * WW + w] = 1e9f;
    sn[w] = 1e9f; sn[2 * WW + w] = 1e9f;
    sp[WW + w] = d2p;
    sn[WW + w] = d2n;
    __syncthreads();

    float bp = d2p, bn = d2n;                  // r = 0 candidates
    const float* cp = sp + WW + w;
    const float* cn = sn + WW + w;
#pragma unroll 1
    for (int r = 1; r < WW; r++) {
        float rr = (float)(r * r);
        if (rr >= bp && rr >= bn) break;       // no larger radius can improve
        // min(a,b)+rr == min(a+rr, b+rr): rounding is monotone, so this is
        // bit-identical to the reference's per-candidate add-then-min.
        bp = fminf(bp, fminf(cp[-r], cp[r]) + rr);
        bn = fminf(bn, fminf(cn[-r], cn[r]) + rr);
    }

    // ---- loss terms ----
    // pred = softmax(logits,axis=1)[:,1] = sigmoid(l1 - l0)
    float l0 = logits[((b * 2 + 0) * HH + h) * WW + w];
    float l1 = logits[((b * 2 + 1) * HH + h) * WW + w];
    float pred = 1.0f / (1.0f + expf(l0 - l1));

    float sdt = sqrtf(bp) - sqrtf(bn);
    float wv  = pred * sdt;
    float cv  = (me == 1) ? 1.0f : 0.0f;

    // ---- deterministic block reduction ----
    unsigned m = 0xFFFFFFFFu;
#pragma unroll
    for (int o = 16; o > 0; o >>= 1) {
        pred += __shfl_down_sync(m, pred, o);
        wv   += __shfl_down_sync(m, wv, o);
        cv   += __shfl_down_sync(m, cv, o);
    }
    __shared__ float rr0[8], rr1[8], rr2[8];
    if ((w & 31) == 0) {
        rr0[w >> 5] = pred; rr1[w >> 5] = wv; rr2[w >> 5] = cv;
    }
    __syncthreads();
    if (w == 0) {
        float s0 = 0.f, s1 = 0.f, s2 = 0.f;
#pragma unroll
        for (int i = 0; i < 8; i++) { s0 += rr0[i]; s1 += rr1[i]; s2 += rr2[i]; }
        g_part_pred[row] = s0;
        g_part_w[row]    = s1;
        g_part_cnt[row]  = s2;
    }
}

// ---------------------------------------------------------------------------
// Final: reduce 256 row-partials per image, apply the s==0 / s==size select,
// average over batch. Single block, deterministic.
// ---------------------------------------------------------------------------
__global__ void final_kernel(float* __restrict__ out) {
    int t = threadIdx.x;           // 256 threads
    __shared__ float red[256];
    float total = 0.0f;

    for (int b = 0; b < BB; b++) {
        float sp = g_part_pred[b * HH + t];
        float sw = g_part_w[b * HH + t];
        float sc = g_part_cnt[b * HH + t];

        red[t] = sp; __syncthreads();
        for (int s = 128; s > 0; s >>= 1) { if (t < s) red[t] += red[t + s]; __syncthreads(); }
        float Sp = red[0]; __syncthreads();
        red[t] = sw; __syncthreads();
        for (int s = 128; s > 0; s >>= 1) { if (t < s) red[t] += red[t + s]; __syncthreads(); }
        float Sw = red[0]; __syncthreads();
        red[t] = sc; __syncthreads();
        for (int s = 128; s > 0; s >>= 1) { if (t < s) red[t] += red[t + s]; __syncthreads(); }
        float Sc = red[0]; __syncthreads();

        if (t == 0) {
            float inv = 1.0f / (float)HW;
            float mean_pred = Sp * inv;
            float mean_w    = Sw * inv;
            float per_b;
            if (Sc == 0.0f)                per_b = mean_pred;
            else if (Sc == (float)HW)      per_b = 1.0f - mean_pred;
            else                           per_b = mean_w;
            total += per_b;
        }
    }
    if (t == 0) out[0] = total / (float)BB;
}

extern "C" void kernel_launch(void* const* d_in, const int* in_sizes, int n_in,
                              void* d_out, int out_size) {
    const float* logits  = (const float*)d_in[0];
    const int*   targets = (const int*)d_in[1];
    float*       out     = (float*)d_out;

    fused_kernel<<<BB * HH, 256>>>(logits, targets);
    final_kernel<<<1, 256>>>(out);
}

// round 3
// speedup vs baseline: 8.3248x; 1.6389x over previous
#include <cuda_runtime.h>
#include <math.h>

#define BB   8
#define HH   256
#define WW   256
#define HW   (HH*WW)

// Scratch (no device allocations allowed): per-row reduction partials.
__device__ float g_part_pred[BB*HH];
__device__ float g_part_w[BB*HH];
__device__ float g_part_cnt[BB*HH];

// ---------------------------------------------------------------------------
// Fused kernel: one block per (b,h) row, one thread per pixel.
//  1. Vertical early-exit search: exact nearest-1 / nearest-0 distance along H.
//  2. Horizontal early-exit lower envelope over smem (bit-exact vs brute force).
//  3. Fused sigmoid/pred, signed-distance weighting, deterministic reduction.
// ---------------------------------------------------------------------------
__global__ void __launch_bounds__(256) fused_kernel(
    const float* __restrict__ logits, const int* __restrict__ targets) {
    int row = blockIdx.x;          // b*256 + h
    int b   = row >> 8;
    int h   = row & 255;
    int w   = threadIdx.x;

    const int* tcol = targets + b * HW + w;   // column w of image b, stride WW
    int me = tcol[h * WW];

    // ---- vertical search: nearest 1 (r1) and nearest 0 (r0) along H ----
    int r1 = 256, r0 = 256;                    // 256 = "not found"
    if (me == 1) r1 = 0; else r0 = 0;
#pragma unroll 1
    for (int r = 1; r < HH; r++) {
        if (r1 < 256 && r0 < 256) break;       // both resolved
        int up = h - r, dn = h + r;
        if (up >= 0) {
            int t = tcol[up * WW];
            if (t == 1) { if (r1 == 256) r1 = r; }
            else        { if (r0 == 256) r0 = r; }
        }
        if (dn < HH) {
            int t = tcol[dn * WW];
            if (t == 1) { if (r1 == 256) r1 = r; }
            else        { if (r0 == 256) r0 = r; }
        }
    }
    float d2p = (r1 < 256) ? (float)(r1 * r1) : 1e9f;   // dist^2 to nearest fg in column
    float d2n = (r0 < 256) ? (float)(r0 * r0) : 1e9f;   // dist^2 to nearest bg in column

    // ---- horizontal lower envelope with BIG-padded smem (no bounds checks) ----
    __shared__ float sp[3 * WW];
    __shared__ float sn[3 * WW];
    sp[w] = 1e9f; sp[2 * WW + w] = 1e9f;
    sn[w] = 1e9f; sn[2 * WW + w] = 1e9f;
    sp[WW + w] = d2p;
    sn[WW + w] = d2n;
    __syncthreads();

    float bp = d2p, bn = d2n;                  // r = 0 candidates
    const float* cp = sp + WW + w;
    const float* cn = sn + WW + w;
#pragma unroll 1
    for (int r = 1; r < WW; r++) {
        float rr = (float)(r * r);
        if (rr >= bp && rr >= bn) break;       // no larger radius can improve
        bp = fminf(bp, fminf(cp[-r], cp[r]) + rr);
        bn = fminf(bn, fminf(cn[-r], cn[r]) + rr);
    }

    // ---- loss terms ----
    // pred = softmax(logits,axis=1)[:,1] = sigmoid(l1 - l0)
    float l0 = logits[((b * 2 + 0) * HH + h) * WW + w];
    float l1 = logits[((b * 2 + 1) * HH + h) * WW + w];
    float pred = 1.0f / (1.0f + expf(l0 - l1));

    float sdt = sqrtf(bp) - sqrtf(bn);
    float wv  = pred * sdt;
    float cv  = (me == 1) ? 1.0f : 0.0f;

    // ---- deterministic block reduction (1 barrier) ----
    unsigned m = 0xFFFFFFFFu;
#pragma unroll
    for (int o = 16; o > 0; o >>= 1) {
        pred += __shfl_down_sync(m, pred, o);
        wv   += __shfl_down_sync(m, wv, o);
        cv   += __shfl_down_sync(m, cv, o);
    }
    __shared__ float rr0[8], rr1[8], rr2[8];
    if ((w & 31) == 0) {
        rr0[w >> 5] = pred; rr1[w >> 5] = wv; rr2[w >> 5] = cv;
    }
    __syncthreads();
    if (w == 0) {
        float s0 = 0.f, s1 = 0.f, s2 = 0.f;
#pragma unroll
        for (int i = 0; i < 8; i++) { s0 += rr0[i]; s1 += rr1[i]; s2 += rr2[i]; }
        g_part_pred[row] = s0;
        g_part_w[row]    = s1;
        g_part_cnt[row]  = s2;
    }
}

// ---------------------------------------------------------------------------
// Final: 8 warps, one per batch image. Strided loads + warp-shuffle tree —
// exactly ONE block barrier. Deterministic (fixed summation order per run).
// ---------------------------------------------------------------------------
__global__ void __launch_bounds__(256) final_kernel(float* __restrict__ out) {
    int t    = threadIdx.x;        // 256 threads = 8 warps
    int wb   = t >> 5;             // batch handled by this warp
    int lane = t & 31;

    float s0 = 0.f, s1 = 0.f, s2 = 0.f;
#pragma unroll
    for (int i = 0; i < 8; i++) {
        int idx = wb * HH + lane + i * 32;
        s0 += g_part_pred[idx];
        s1 += g_part_w[idx];
        s2 += g_part_cnt[idx];
    }

    unsigned m = 0xFFFFFFFFu;
#pragma unroll
    for (int o = 16; o > 0; o >>= 1) {
        s0 += __shfl_down_sync(m, s0, o);
        s1 += __shfl_down_sync(m, s1, o);
        s2 += __shfl_down_sync(m, s2, o);
    }

    __shared__ float pb[8];
    if (lane == 0) {
        float inv = 1.0f / (float)HW;
        float mean_pred = s0 * inv;
        float mean_w    = s1 * inv;
        float per_b;
        if (s2 == 0.0f)           per_b = mean_pred;
        else if (s2 == (float)HW) per_b = 1.0f - mean_pred;
        else                      per_b = mean_w;
        pb[wb] = per_b;
    }
    __syncthreads();
    if (t == 0) {
        float total = 0.f;
#pragma unroll
        for (int i = 0; i < BB; i++) total += pb[i];
        out[0] = total / (float)BB;
    }
}

extern "C" void kernel_launch(void* const* d_in, const int* in_sizes, int n_in,
                              void* d_out, int out_size) {
    const float* logits  = (const float*)d_in[0];
    const int*   targets = (const int*)d_in[1];
    float*       out     = (float*)d_out;

    fused_kernel<<<BB * HH, 256>>>(logits, targets);
    final_kernel<<<1, 256>>>(out);
}